// round 8
// baseline (speedup 1.0000x reference)
#include <cuda_runtime.h>
#include <math.h>

#define BB 64
#define TT 32
#define CC 2048
#define DD 1024

// Scratch (__device__ globals; allocation-free rule)
__device__ float g_XN[BB * TT * CC];   // noise-mixed input (16 MB)
__device__ float g_H [TT * BB * DD];   // gelu(enc1 out)
__device__ float g_H2[TT * BB * DD];   // enc2 out (pre-LN)
__device__ float g_Z [TT * BB * DD];   // latent
__device__ float g_G [TT * BB * DD];   // gelu(dec1 out)

__device__ __forceinline__ float gelu_f(float x) {
    return 0.5f * x * (1.0f + erff(x * 0.70710678118654752440f));
}

// Packed fp32x2 FMA (Blackwell): acc = a*b + acc elementwise on both halves.
#define FFMA2(acc, a, b) asm("fma.rn.f32x2 %0, %1, %2, %0;" : "+l"(acc) : "l"(a), "l"(b))
#define PACK2(d, x)      asm("mov.b64 %0, {%1, %1};" : "=l"(d) : "r"(__float_as_uint(x)))
#define LDSV2U64(d0, d1, a) asm("ld.shared.v2.u64 {%0, %1}, [%2];" : "=l"(d0), "=l"(d1) : "r"(a))
#define UNPACK2(lo, hi, v)  asm("mov.b64 {%0, %1}, %2;" : "=f"(lo), "=f"(hi) : "l"(v))

// ---------------------------------------------------------------------------
// Noise-mix pre-pass: xn = noise_x * 1e-4 + x * (1 - 1e-4)
// ---------------------------------------------------------------------------
__global__ __launch_bounds__(256) void mix_kernel(
    const float* __restrict__ x, const float* __restrict__ nx,
    float* __restrict__ xn, int n4)
{
    int i = blockIdx.x * 256 + threadIdx.x;
    if (i >= n4) return;
    float4 a = reinterpret_cast<const float4*>(x)[i];
    float4 b = reinterpret_cast<const float4*>(nx)[i];
    const float f = 1e-4f, g = 1.0f - 1e-4f;
    float4 o;
    o.x = b.x * f + a.x * g;
    o.y = b.y * f + a.y * g;
    o.z = b.z * f + a.z * g;
    o.w = b.w * f + a.w * g;
    reinterpret_cast<float4*>(xn)[i] = o;
}

// ---------------------------------------------------------------------------
// Batched GEMM: C[t] (64 x N) = A[t] (64 x K) @ Bw[t] (K x N)
// BM=64, BN=128, BK=16. 128 threads (4 warps). Per-thread tile 8(m) x 8(n):
// 32 packed-f32x2 FMAs per k-step. Grid = (N/128, T) -> 256-512 blocks.
// Thread map: tx = tid&15 -> cols tx*8..tx*8+7; ty = tid>>4 -> rows ty*8..+7.
// ---------------------------------------------------------------------------
template<bool GELU_EPI>
__global__ __launch_bounds__(128, 2) void gemm64x128(
    const float* __restrict__ A, long a_tstride, int lda,
    const float* __restrict__ Bw,           // [T][K][N]
    float* __restrict__ Co, long c_tstride, int ldc,
    int K, int N)
{
    const int t   = blockIdx.y;
    const int nb  = blockIdx.x * 128;
    const int tid = threadIdx.x;
    const int tx  = tid & 15;
    const int ty  = tid >> 4;

    __shared__ __align__(16) float As[16][68];    // [k][m], padded
    __shared__ __align__(16) float Bs[16][128];   // [k][n]

    // Global load mapping
    const int ar  = tid >> 1;            // A row 0..63
    const int akq = (tid & 1) * 8;       // A k-offset 0 or 8 (2x float4)
    const int br  = tid >> 3;            // B k-row 0..15
    const int bc  = (tid & 7) * 16;      // B col base (16 floats per thread)

    const float* Ab = A + (long)t * a_tstride + (long)ar * lda + akq;
    const float* Bb = Bw + (long)t * K * N + nb + bc;

    unsigned long long acc[8][4];        // [m-row][n-pair]
    #pragma unroll
    for (int r = 0; r < 8; r++)
        #pragma unroll
        for (int j = 0; j < 4; j++) acc[r][j] = 0ull;

    // Prefetch first tile into registers
    float4 pa0, pa1, pb[4];
    pa0 = *reinterpret_cast<const float4*>(Ab);
    pa1 = *reinterpret_cast<const float4*>(Ab + 4);
    #pragma unroll
    for (int q = 0; q < 4; q++)
        pb[q] = *reinterpret_cast<const float4*>(Bb + (long)br * N + q * 4);

    unsigned sB = (unsigned)__cvta_generic_to_shared(&Bs[0][0]);

    for (int kt = 0; kt < K; kt += 16) {
        // Fill smem from prefetch regs
        #pragma unroll
        for (int j = 0; j < 4; j++) {
            As[akq + j][ar]     = (&pa0.x)[j];
            As[akq + 4 + j][ar] = (&pa1.x)[j];
        }
        #pragma unroll
        for (int q = 0; q < 4; q++)
            *reinterpret_cast<float4*>(&Bs[br][bc + q * 4]) = pb[q];
        __syncthreads();

        // Prefetch next tile (overlaps compute)
        if (kt + 16 < K) {
            pa0 = *reinterpret_cast<const float4*>(Ab + kt + 16);
            pa1 = *reinterpret_cast<const float4*>(Ab + kt + 20);
            #pragma unroll
            for (int q = 0; q < 4; q++)
                pb[q] = *reinterpret_cast<const float4*>(
                    Bb + (long)(kt + 16 + br) * N + q * 4);
        }

        // Compute 16 k-steps
        #pragma unroll
        for (int k = 0; k < 16; k++) {
            unsigned long long b64[4];
            {
                unsigned addr = sB + (unsigned)((k * 128 + tx * 8) << 2);
                LDSV2U64(b64[0], b64[1], addr);
                LDSV2U64(b64[2], b64[3], addr + 16);
            }
            float4 av0 = *reinterpret_cast<const float4*>(&As[k][ty * 8]);
            float4 av1 = *reinterpret_cast<const float4*>(&As[k][ty * 8 + 4]);
            unsigned long long a64[8];
            PACK2(a64[0], av0.x); PACK2(a64[1], av0.y);
            PACK2(a64[2], av0.z); PACK2(a64[3], av0.w);
            PACK2(a64[4], av1.x); PACK2(a64[5], av1.y);
            PACK2(a64[6], av1.z); PACK2(a64[7], av1.w);
            #pragma unroll
            for (int r = 0; r < 8; r++)
                #pragma unroll
                for (int j = 0; j < 4; j++)
                    FFMA2(acc[r][j], a64[r], b64[j]);
        }
        __syncthreads();
    }

    // Epilogue: rows ty*8..+7, cols tx*8..+7
    float* Cb = Co + (long)t * c_tstride + nb + tx * 8;
    #pragma unroll
    for (int r = 0; r < 8; r++) {
        float* row = Cb + (long)(ty * 8 + r) * ldc;
        float v0, v1, v2, v3, v4, v5, v6, v7;
        UNPACK2(v0, v1, acc[r][0]);
        UNPACK2(v2, v3, acc[r][1]);
        UNPACK2(v4, v5, acc[r][2]);
        UNPACK2(v6, v7, acc[r][3]);
        float4 o0, o1;
        if (GELU_EPI) {
            o0.x = gelu_f(v0); o0.y = gelu_f(v1); o0.z = gelu_f(v2); o0.w = gelu_f(v3);
            o1.x = gelu_f(v4); o1.y = gelu_f(v5); o1.z = gelu_f(v6); o1.w = gelu_f(v7);
        } else {
            o0.x = v0; o0.y = v1; o0.z = v2; o0.w = v3;
            o1.x = v4; o1.y = v5; o1.z = v6; o1.w = v7;
        }
        *reinterpret_cast<float4*>(row)     = o0;
        *reinterpret_cast<float4*>(row + 4) = o1;
    }
}

// ---------------------------------------------------------------------------
// Fused LayerNorm + latent noise + clamp. One block per row r=t*BB+b, D=1024.
// noise_z layout is [b][t][d].
// ---------------------------------------------------------------------------
__global__ __launch_bounds__(256) void ln_kernel(
    const float* __restrict__ H2, const float* __restrict__ noise_z,
    const float* __restrict__ gamma, const float* __restrict__ beta,
    float* __restrict__ Z)
{
    const int r = blockIdx.x;
    const int t = r >> 6;
    const int b = r & 63;
    const int tid = threadIdx.x;

    const float* h  = H2 + (long)r * DD;
    const float* nz = noise_z + ((long)b * TT + t) * DD;
    float*       z  = Z + (long)r * DD;

    float4 hv = *reinterpret_cast<const float4*>(h + tid * 4);
    float s  = hv.x + hv.y + hv.z + hv.w;
    float ss = hv.x * hv.x + hv.y * hv.y + hv.z * hv.z + hv.w * hv.w;

    #pragma unroll
    for (int off = 16; off > 0; off >>= 1) {
        s  += __shfl_xor_sync(0xffffffffu, s,  off);
        ss += __shfl_xor_sync(0xffffffffu, ss, off);
    }
    __shared__ float ws[8], wss[8];
    const int lane = tid & 31, wid = tid >> 5;
    if (lane == 0) { ws[wid] = s; wss[wid] = ss; }
    __syncthreads();

    float mu = 0.f, m2 = 0.f;
    #pragma unroll
    for (int i = 0; i < 8; i++) { mu += ws[i]; m2 += wss[i]; }
    mu *= (1.0f / DD);
    float var  = m2 * (1.0f / DD) - mu * mu;
    float rstd = rsqrtf(var + 1e-5f);

    float4 nv = *reinterpret_cast<const float4*>(nz + tid * 4);
    float4 g4 = *reinterpret_cast<const float4*>(gamma + tid * 4);
    float4 b4 = *reinterpret_cast<const float4*>(beta + tid * 4);

    const float fl = 1e-3f, gl = 1.0f - 1e-3f;
    float4 ov; float v;
    v = (hv.x - mu) * rstd * g4.x + b4.x; v = nv.x * fl + v * gl; ov.x = fminf(1.0f, fmaxf(-1.0f, v));
    v = (hv.y - mu) * rstd * g4.y + b4.y; v = nv.y * fl + v * gl; ov.y = fminf(1.0f, fmaxf(-1.0f, v));
    v = (hv.z - mu) * rstd * g4.z + b4.z; v = nv.z * fl + v * gl; ov.z = fminf(1.0f, fmaxf(-1.0f, v));
    v = (hv.w - mu) * rstd * g4.w + b4.w; v = nv.w * fl + v * gl; ov.w = fminf(1.0f, fmaxf(-1.0f, v));
    *reinterpret_cast<float4*>(z + tid * 4) = ov;
}

extern "C" void kernel_launch(void* const* d_in, const int* in_sizes, int n_in,
                              void* d_out, int out_size) {
    const float* x       = (const float*)d_in[0];
    const float* noise_x = (const float*)d_in[1];
    const float* noise_z = (const float*)d_in[2];
    const float* enc_w1  = (const float*)d_in[3];   // [T][C][D]
    const float* enc_w2  = (const float*)d_in[4];   // [T][D][D]
    const float* dec_w1  = (const float*)d_in[5];   // [T][D][D]
    const float* dec_w2  = (const float*)d_in[6];   // [T][D][C]
    const float* ln_g    = (const float*)d_in[7];
    const float* ln_b    = (const float*)d_in[8];
    float* out = (float*)d_out;

    float *XN, *H, *H2, *Z, *G;
    cudaGetSymbolAddress((void**)&XN, g_XN);
    cudaGetSymbolAddress((void**)&H,  g_H);
    cudaGetSymbolAddress((void**)&H2, g_H2);
    cudaGetSymbolAddress((void**)&Z,  g_Z);
    cudaGetSymbolAddress((void**)&G,  g_G);

    // 0) noise-mix x into dedicated scratch
    {
        int n4 = BB * TT * CC / 4;
        mix_kernel<<<n4 / 256, 256>>>(x, noise_x, XN, n4);
    }

    // 1) enc1: H[t][b][d] = gelu( xn_chunk @ enc_w1[t] )   (256 blocks)
    gemm64x128<true><<<dim3(DD / 128, TT), 128>>>(
        XN, (long)CC, TT * CC, enc_w1, H, (long)BB * DD, DD, CC, DD);

    // 2) enc2: H2 = H @ enc_w2[t]                          (256 blocks)
    gemm64x128<false><<<dim3(DD / 128, TT), 128>>>(
        H, (long)BB * DD, DD, enc_w2, H2, (long)BB * DD, DD, DD, DD);

    // 3) LayerNorm + latent noise + clamp -> Z
    ln_kernel<<<TT * BB, 256>>>(H2, noise_z, ln_g, ln_b, Z);

    // 4) dec1: G = gelu( Z @ dec_w1[t] )                   (256 blocks)
    gemm64x128<true><<<dim3(DD / 128, TT), 128>>>(
        Z, (long)BB * DD, DD, dec_w1, G, (long)BB * DD, DD, DD, DD);

    // 5) dec2: out[b][t*C + c] = G @ dec_w2[t]             (512 blocks)
    gemm64x128<false><<<dim3(CC / 128, TT), 128>>>(
        G, (long)BB * DD, DD, dec_w2, out, (long)CC, TT * CC, DD, CC);
}

// round 10
// speedup vs baseline: 1.0925x; 1.0925x over previous
#include <cuda_runtime.h>
#include <math.h>
#include <stdint.h>

#define BB 64
#define TT 32
#define CC 2048
#define DD 1024

// Scratch (__device__ globals; allocation-free rule)
__device__ float g_XN[BB * TT * CC];   // noise-mixed input (16 MB)
__device__ float g_H [TT * BB * DD];
__device__ float g_H2[TT * BB * DD];
__device__ float g_Z [TT * BB * DD];
__device__ float g_G [TT * BB * DD];

__device__ __forceinline__ float gelu_f(float x) {
    return 0.5f * x * (1.0f + erff(x * 0.70710678118654752440f));
}

__device__ __forceinline__ uint32_t f2tf(float x) {
    uint32_t r;
    asm("cvt.rna.tf32.f32 %0, %1;" : "=r"(r) : "f"(x));
    return r;
}

// acc += A(16x8 tf32) @ B(8x8 tf32), fp32 accum
#define MMA_TF32(c, a, b) \
    asm volatile("mma.sync.aligned.m16n8k8.row.col.f32.tf32.tf32.f32 " \
                 "{%0,%1,%2,%3}, {%4,%5,%6,%7}, {%8,%9}, {%0,%1,%2,%3};" \
                 : "+f"((c)[0]), "+f"((c)[1]), "+f"((c)[2]), "+f"((c)[3]) \
                 : "r"((a)[0]), "r"((a)[1]), "r"((a)[2]), "r"((a)[3]), \
                   "r"((b)[0]), "r"((b)[1]))

// smem word offsets (fp32/tf32 words)
#define AHI_OFF 0
#define ALO_OFF 2304            // 64 * 36
#define WHI_OFF 4608
#define WLO_OFF 8960            // + 32 * 136
#define SM_WORDS 13312          // 53248 bytes
#define A_PAD 36
#define W_PAD 136
#define C_PAD 132

// ---------------------------------------------------------------------------
// Batched GEMM via 3xTF32 mma.sync: C[t](64 x N) = Act[t](64 x K) @ W[t](K x N)
// Block: 256 thr, tile 64m x 128n, BK=32. Warp (wm = wid&1, wn = wid>>1)
// computes 32m x 32n with m16n8k8 frags: 2 m-frags x 4 n-frags.
// ---------------------------------------------------------------------------
template<bool GELU_EPI>
__global__ __launch_bounds__(256) void gemm_mma(
    const float* __restrict__ Act, long act_t, int act_ld,
    const float* __restrict__ W, int N, int K,
    float* __restrict__ C, long c_t, int c_ld)
{
    extern __shared__ __align__(16) uint32_t sm[];
    const int t     = blockIdx.y;
    const int ntile = blockIdx.x;
    const int tid   = threadIdx.x;
    const int wid   = tid >> 5;
    const int lid   = tid & 31;
    const int wm    = wid & 1;         // 0..1
    const int wn    = wid >> 1;        // 0..3
    const int g     = lid >> 2;        // group 0..7
    const int tg    = lid & 3;         // thread-in-group

    const float* At = Act + (long)t * act_t;
    const float* Wt = W + (long)t * K * N + ntile * 128;

    float acc[2][4][4];
    #pragma unroll
    for (int i = 0; i < 2; i++)
        #pragma unroll
        for (int j = 0; j < 4; j++)
            #pragma unroll
            for (int r = 0; r < 4; r++) acc[i][j][r] = 0.f;

    // staging maps
    const int s_ar = tid >> 2;          // A row 0..63
    const int s_ak = (tid & 3) * 8;     // A k base (two float4)
    const int s_wk = tid >> 3;          // W k row 0..31
    const int s_wn = (tid & 7) * 16;    // W n base (four float4)

    for (int kc = 0; kc < K; kc += 32) {
        // ---- stage A tile (64 x 32) as tf32 hi/lo
        {
            const float* ap = At + (long)s_ar * act_ld + kc + s_ak;
            float4 v0 = *(const float4*)(ap);
            float4 v1 = *(const float4*)(ap + 4);
            uint32_t* ah = sm + AHI_OFF + s_ar * A_PAD + s_ak;
            uint32_t* al = sm + ALO_OFF + s_ar * A_PAD + s_ak;
            #pragma unroll
            for (int j = 0; j < 4; j++) {
                float x = (&v0.x)[j];
                uint32_t h = f2tf(x);
                ah[j] = h;
                al[j] = f2tf(x - __uint_as_float(h));
            }
            #pragma unroll
            for (int j = 0; j < 4; j++) {
                float x = (&v1.x)[j];
                uint32_t h = f2tf(x);
                ah[4 + j] = h;
                al[4 + j] = f2tf(x - __uint_as_float(h));
            }
        }
        // ---- stage W tile (32 x 128) as tf32 hi/lo
        {
            const float* wp = Wt + (long)(kc + s_wk) * N + s_wn;
            uint32_t* wh = sm + WHI_OFF + s_wk * W_PAD + s_wn;
            uint32_t* wl = sm + WLO_OFF + s_wk * W_PAD + s_wn;
            #pragma unroll
            for (int q = 0; q < 4; q++) {
                float4 v = *(const float4*)(wp + q * 4);
                #pragma unroll
                for (int j = 0; j < 4; j++) {
                    float x = (&v.x)[j];
                    uint32_t h = f2tf(x);
                    wh[q * 4 + j] = h;
                    wl[q * 4 + j] = f2tf(x - __uint_as_float(h));
                }
            }
        }
        __syncthreads();

        // ---- compute: 4 k-steps of 8
        #pragma unroll
        for (int ks = 0; ks < 4; ks++) {
            const int k0 = ks * 8;
            uint32_t ahi[2][4], alo[2][4], bhi[4][2], blo[4][2];
            #pragma unroll
            for (int mt = 0; mt < 2; mt++) {
                int m = wm * 32 + mt * 16 + g;
                int i0 = m * A_PAD + k0 + tg;
                int i1 = (m + 8) * A_PAD + k0 + tg;
                ahi[mt][0] = sm[AHI_OFF + i0];
                ahi[mt][1] = sm[AHI_OFF + i1];
                ahi[mt][2] = sm[AHI_OFF + i0 + 4];
                ahi[mt][3] = sm[AHI_OFF + i1 + 4];
                alo[mt][0] = sm[ALO_OFF + i0];
                alo[mt][1] = sm[ALO_OFF + i1];
                alo[mt][2] = sm[ALO_OFF + i0 + 4];
                alo[mt][3] = sm[ALO_OFF + i1 + 4];
            }
            #pragma unroll
            for (int nt = 0; nt < 4; nt++) {
                int n = wn * 32 + nt * 8 + g;
                int i0 = (k0 + tg) * W_PAD + n;
                int i1 = (k0 + tg + 4) * W_PAD + n;
                bhi[nt][0] = sm[WHI_OFF + i0];
                bhi[nt][1] = sm[WHI_OFF + i1];
                blo[nt][0] = sm[WLO_OFF + i0];
                blo[nt][1] = sm[WLO_OFF + i1];
            }
            #pragma unroll
            for (int mt = 0; mt < 2; mt++)
                #pragma unroll
                for (int nt = 0; nt < 4; nt++) {
                    MMA_TF32(acc[mt][nt], ahi[mt], bhi[nt]);
                    MMA_TF32(acc[mt][nt], ahi[mt], blo[nt]);
                    MMA_TF32(acc[mt][nt], alo[mt], bhi[nt]);
                }
        }
        __syncthreads();
    }

    // ---- epilogue: stage C (64 x 128) in smem for coalesced stores
    float* Csm = (float*)sm;           // [64][C_PAD]
    #pragma unroll
    for (int mt = 0; mt < 2; mt++) {
        #pragma unroll
        for (int nt = 0; nt < 4; nt++) {
            int row = wm * 32 + mt * 16 + g;
            int col = wn * 32 + nt * 8 + 2 * tg;
            float v0 = acc[mt][nt][0], v1 = acc[mt][nt][1];
            float v2 = acc[mt][nt][2], v3 = acc[mt][nt][3];
            if (GELU_EPI) {
                v0 = gelu_f(v0); v1 = gelu_f(v1);
                v2 = gelu_f(v2); v3 = gelu_f(v3);
            }
            *(float2*)(Csm + row * C_PAD + col)       = make_float2(v0, v1);
            *(float2*)(Csm + (row + 8) * C_PAD + col) = make_float2(v2, v3);
        }
    }
    __syncthreads();

    float* Cg = C + (long)t * c_t + ntile * 128;
    #pragma unroll
    for (int i = 0; i < 8; i++) {
        int idx = tid + i * 256;       // 2048 float4
        int b = idx >> 5, c4 = idx & 31;
        float4 v = *(float4*)(Csm + b * C_PAD + c4 * 4);
        *(float4*)(Cg + (long)b * c_ld + c4 * 4) = v;
    }
}

// ---------------------------------------------------------------------------
// Noise-mix pre-pass: xn = noise_x * 1e-4 + x * (1 - 1e-4)
// ---------------------------------------------------------------------------
__global__ __launch_bounds__(256) void mix_kernel(
    const float* __restrict__ x, const float* __restrict__ nx,
    float* __restrict__ xn, int n4)
{
    int i = blockIdx.x * 256 + threadIdx.x;
    if (i >= n4) return;
    float4 a = reinterpret_cast<const float4*>(x)[i];
    float4 b = reinterpret_cast<const float4*>(nx)[i];
    const float f = 1e-4f, g = 1.0f - 1e-4f;
    float4 o;
    o.x = b.x * f + a.x * g;
    o.y = b.y * f + a.y * g;
    o.z = b.z * f + a.z * g;
    o.w = b.w * f + a.w * g;
    reinterpret_cast<float4*>(xn)[i] = o;
}

// ---------------------------------------------------------------------------
// Fused LayerNorm + latent noise + clamp. One block per row r=t*BB+b, D=1024.
// noise_z layout is [b][t][d].
// ---------------------------------------------------------------------------
__global__ __launch_bounds__(256) void ln_kernel(
    const float* __restrict__ H2, const float* __restrict__ noise_z,
    const float* __restrict__ gamma, const float* __restrict__ beta,
    float* __restrict__ Z)
{
    const int r = blockIdx.x;
    const int t = r >> 6;
    const int b = r & 63;
    const int tid = threadIdx.x;

    const float* h  = H2 + (long)r * DD;
    const float* nz = noise_z + ((long)b * TT + t) * DD;
    float*       z  = Z + (long)r * DD;

    float4 hv = *reinterpret_cast<const float4*>(h + tid * 4);
    float s  = hv.x + hv.y + hv.z + hv.w;
    float ss = hv.x * hv.x + hv.y * hv.y + hv.z * hv.z + hv.w * hv.w;

    #pragma unroll
    for (int off = 16; off > 0; off >>= 1) {
        s  += __shfl_xor_sync(0xffffffffu, s,  off);
        ss += __shfl_xor_sync(0xffffffffu, ss, off);
    }
    __shared__ float ws[8], wss[8];
    const int lane = tid & 31, wrp = tid >> 5;
    if (lane == 0) { ws[wrp] = s; wss[wrp] = ss; }
    __syncthreads();

    float mu = 0.f, m2 = 0.f;
    #pragma unroll
    for (int i = 0; i < 8; i++) { mu += ws[i]; m2 += wss[i]; }
    mu *= (1.0f / DD);
    float var  = m2 * (1.0f / DD) - mu * mu;
    float rstd = rsqrtf(var + 1e-5f);

    float4 nv = *reinterpret_cast<const float4*>(nz + tid * 4);
    float4 g4 = *reinterpret_cast<const float4*>(gamma + tid * 4);
    float4 b4 = *reinterpret_cast<const float4*>(beta + tid * 4);

    const float fl = 1e-3f, gl = 1.0f - 1e-3f;
    float4 ov; float v;
    v = (hv.x - mu) * rstd * g4.x + b4.x; v = nv.x * fl + v * gl; ov.x = fminf(1.0f, fmaxf(-1.0f, v));
    v = (hv.y - mu) * rstd * g4.y + b4.y; v = nv.y * fl + v * gl; ov.y = fminf(1.0f, fmaxf(-1.0f, v));
    v = (hv.z - mu) * rstd * g4.z + b4.z; v = nv.z * fl + v * gl; ov.z = fminf(1.0f, fmaxf(-1.0f, v));
    v = (hv.w - mu) * rstd * g4.w + b4.w; v = nv.w * fl + v * gl; ov.w = fminf(1.0f, fmaxf(-1.0f, v));
    *reinterpret_cast<float4*>(z + tid * 4) = ov;
}

extern "C" void kernel_launch(void* const* d_in, const int* in_sizes, int n_in,
                              void* d_out, int out_size) {
    const float* x       = (const float*)d_in[0];
    const float* noise_x = (const float*)d_in[1];
    const float* noise_z = (const float*)d_in[2];
    const float* enc_w1  = (const float*)d_in[3];   // [T][C][D]
    const float* enc_w2  = (const float*)d_in[4];   // [T][D][D]
    const float* dec_w1  = (const float*)d_in[5];   // [T][D][D]
    const float* dec_w2  = (const float*)d_in[6];   // [T][D][C]
    const float* ln_g    = (const float*)d_in[7];
    const float* ln_b    = (const float*)d_in[8];
    float* out = (float*)d_out;

    float *XN, *H, *H2, *Z, *G;
    cudaGetSymbolAddress((void**)&XN, g_XN);
    cudaGetSymbolAddress((void**)&H,  g_H);
    cudaGetSymbolAddress((void**)&H2, g_H2);
    cudaGetSymbolAddress((void**)&Z,  g_Z);
    cudaGetSymbolAddress((void**)&G,  g_G);

    const int smem_bytes = SM_WORDS * 4;   // 53248
    cudaFuncSetAttribute(gemm_mma<true>,  cudaFuncAttributeMaxDynamicSharedMemorySize, smem_bytes);
    cudaFuncSetAttribute(gemm_mma<false>, cudaFuncAttributeMaxDynamicSharedMemorySize, smem_bytes);

    // 0) noise-mix x
    {
        int n4 = BB * TT * CC / 4;
        mix_kernel<<<n4 / 256, 256>>>(x, noise_x, XN, n4);
    }

    // 1) enc1: H = gelu(XN_chunk @ enc_w1[t])   K=2048, N=1024
    gemm_mma<true><<<dim3(DD / 128, TT), 256, smem_bytes>>>(
        XN, (long)CC, TT * CC, enc_w1, DD, CC, H, (long)BB * DD, DD);

    // 2) enc2: H2 = H @ enc_w2[t]               K=1024, N=1024
    gemm_mma<false><<<dim3(DD / 128, TT), 256, smem_bytes>>>(
        H, (long)BB * DD, DD, enc_w2, DD, DD, H2, (long)BB * DD, DD);

    // 3) LayerNorm + latent noise + clamp
    ln_kernel<<<TT * BB, 256>>>(H2, noise_z, ln_g, ln_b, Z);

    // 4) dec1: G = gelu(Z @ dec_w1[t])           K=1024, N=1024
    gemm_mma<true><<<dim3(DD / 128, TT), 256, smem_bytes>>>(
        Z, (long)BB * DD, DD, dec_w1, DD, DD, G, (long)BB * DD, DD);

    // 5) dec2: out = G @ dec_w2[t]               K=1024, N=2048
    gemm_mma<false><<<dim3(CC / 128, TT), 256, smem_bytes>>>(
        G, (long)BB * DD, DD, dec_w2, CC, DD, out, (long)CC, TT * CC);
}